// round 1
// baseline (speedup 1.0000x reference)
#include <cuda_runtime.h>
#include <math.h>

#define B_SZ   8192
#define D_SZ   256
#define BM     64
#define BN     64
#define BK     64
#define NTHREADS 256

// A-stripe row stride (floats): 256 + 4 pad
#define AS_STRIDE 260
// B-tile row stride (floats): 64 + 4 pad  (68 mod 32 == 4 -> 2-way max on LDS.128)
#define BS_STRIDE 68

static __device__ float g_norm[B_SZ * D_SZ];   // normalized embeddings (8 MB scratch)
static __device__ float g_loss;
static __device__ float g_count;

__global__ void init_accum_kernel() {
    g_loss = 0.0f;
    g_count = 0.0f;
}

// One warp per row: L2-normalize (with max(norm,1e-12) like the reference).
__global__ __launch_bounds__(256) void normalize_kernel(const float* __restrict__ emb) {
    int row  = blockIdx.x * 8 + (threadIdx.x >> 5);
    int lane = threadIdx.x & 31;
    const float4* src = reinterpret_cast<const float4*>(emb) + (size_t)row * (D_SZ / 4);
    float4 v0 = src[lane];
    float4 v1 = src[lane + 32];
    float s = v0.x * v0.x + v0.y * v0.y + v0.z * v0.z + v0.w * v0.w
            + v1.x * v1.x + v1.y * v1.y + v1.z * v1.z + v1.w * v1.w;
#pragma unroll
    for (int o = 16; o > 0; o >>= 1) s += __shfl_xor_sync(0xffffffffu, s, o);
    float scale = 1.0f / fmaxf(sqrtf(s), 1e-12f);
    v0.x *= scale; v0.y *= scale; v0.z *= scale; v0.w *= scale;
    v1.x *= scale; v1.y *= scale; v1.z *= scale; v1.w *= scale;
    float4* dst = reinterpret_cast<float4*>(g_norm) + (size_t)row * (D_SZ / 4);
    dst[lane]      = v0;
    dst[lane + 32] = v1;
}

// Each block owns rows [blockIdx.x*64, +64), sweeps all 8192 columns in 64-wide
// tiles, computing exp(sim) epilogue fused with per-row all/pos sums.
__global__ __launch_bounds__(NTHREADS) void loss_kernel(const int* __restrict__ ids) {
    extern __shared__ unsigned char smem_raw[];
    float* As     = reinterpret_cast<float*>(smem_raw);          // 64 x 260
    float* Bs     = As + BM * AS_STRIDE;                         // 64 x 68
    int*   idsA   = reinterpret_cast<int*>(Bs + BN * BS_STRIDE); // 64
    int*   idsB   = idsA + BM;                                   // 64
    float* rowAll = reinterpret_cast<float*>(idsB + BN);         // 64
    float* rowPos = rowAll + BM;                                 // 64

    const int tid = threadIdx.x;
    const int tx  = tid & 15;    // 16 col-threads
    const int ty  = tid >> 4;    // 16 row-threads
    const int r0  = blockIdx.x * BM;

    const float INV_T = 1.0f / 0.07f;

    // Load the full 64 x 256 A stripe once (16 KB floats -> 64 KB).
#pragma unroll
    for (int t = tid; t < BM * (D_SZ / 4); t += NTHREADS) {
        int row = t >> 6;          // /64 float4 per row
        int c4  = t & 63;
        float4 v = *reinterpret_cast<const float4*>(g_norm + (size_t)(r0 + row) * D_SZ + c4 * 4);
        *reinterpret_cast<float4*>(As + row * AS_STRIDE + c4 * 4) = v;
    }
    if (tid < BM) {
        idsA[tid]   = ids[r0 + tid];
        rowAll[tid] = 0.0f;
        rowPos[tid] = 0.0f;
    }
    __syncthreads();

    int myIdA[4];
#pragma unroll
    for (int ii = 0; ii < 4; ii++) myIdA[ii] = idsA[ty * 4 + ii];

    float allAcc[4] = {0.f, 0.f, 0.f, 0.f};
    float posAcc[4] = {0.f, 0.f, 0.f, 0.f};

    for (int ct = 0; ct < B_SZ / BN; ct++) {
        const int c0 = ct * BN;
        float acc[4][4];
#pragma unroll
        for (int ii = 0; ii < 4; ii++)
#pragma unroll
            for (int jj = 0; jj < 4; jj++) acc[ii][jj] = 0.0f;

        for (int kk = 0; kk < D_SZ; kk += BK) {
            // Load 64 x 64 B chunk (1024 float4, 4 per thread).
#pragma unroll
            for (int t = tid; t < BN * (BK / 4); t += NTHREADS) {
                int row = t >> 4;     // /16 float4 per row
                int c4  = t & 15;
                float4 v = *reinterpret_cast<const float4*>(
                    g_norm + (size_t)(c0 + row) * D_SZ + kk + c4 * 4);
                *reinterpret_cast<float4*>(Bs + row * BS_STRIDE + c4 * 4) = v;
            }
            if (kk == 0 && tid < BN) idsB[tid] = ids[c0 + tid];
            __syncthreads();

#pragma unroll
            for (int k = 0; k < BK; k += 4) {
                float4 a[4], b[4];
#pragma unroll
                for (int ii = 0; ii < 4; ii++)
                    a[ii] = *reinterpret_cast<const float4*>(As + (ty * 4 + ii) * AS_STRIDE + kk + k);
#pragma unroll
                for (int jj = 0; jj < 4; jj++)
                    b[jj] = *reinterpret_cast<const float4*>(Bs + (tx * 4 + jj) * BS_STRIDE + k);
#pragma unroll
                for (int ii = 0; ii < 4; ii++) {
#pragma unroll
                    for (int jj = 0; jj < 4; jj++) {
                        acc[ii][jj] = fmaf(a[ii].x, b[jj].x, acc[ii][jj]);
                        acc[ii][jj] = fmaf(a[ii].y, b[jj].y, acc[ii][jj]);
                        acc[ii][jj] = fmaf(a[ii].z, b[jj].z, acc[ii][jj]);
                        acc[ii][jj] = fmaf(a[ii].w, b[jj].w, acc[ii][jj]);
                    }
                }
            }
            __syncthreads();
        }

        // Epilogue: exp with diag mask, accumulate all/pos per row.
#pragma unroll
        for (int jj = 0; jj < 4; jj++) {
            const int gj  = c0 + tx * 4 + jj;
            const int idB = idsB[tx * 4 + jj];
#pragma unroll
            for (int ii = 0; ii < 4; ii++) {
                const int gi = r0 + ty * 4 + ii;
                float e = (gi == gj) ? 0.0f : __expf(acc[ii][jj] * INV_T);
                allAcc[ii] += e;
                if (myIdA[ii] == idB) posAcc[ii] += e;
            }
        }
        __syncthreads();  // protect idsB before next tile's rewrite
    }

    // Reduce per-row sums across the 16 tx threads sharing each row.
#pragma unroll
    for (int ii = 0; ii < 4; ii++) {
        atomicAdd(&rowAll[ty * 4 + ii], allAcc[ii]);
        atomicAdd(&rowPos[ty * 4 + ii], posAcc[ii]);
    }
    __syncthreads();

    float pr = 0.0f, vd = 0.0f;
    if (tid < BM) {
        float p = rowPos[tid];
        float a = rowAll[tid];
        if (p > 0.0f) {
            pr = -logf(p / a);
            vd = 1.0f;
        }
    }
#pragma unroll
    for (int o = 16; o > 0; o >>= 1) {
        pr += __shfl_xor_sync(0xffffffffu, pr, o);
        vd += __shfl_xor_sync(0xffffffffu, vd, o);
    }
    if ((tid & 31) == 0 && pr != 0.0f + vd * 0.0f) {  // keep all warps' lane0 contributing
        atomicAdd(&g_loss, pr);
        atomicAdd(&g_count, vd);
    }
}

__global__ void finalize_kernel(float* __restrict__ out) {
    out[0] = g_loss / fmaxf(g_count, 1.0f);
}

extern "C" void kernel_launch(void* const* d_in, const int* in_sizes, int n_in,
                              void* d_out, int out_size) {
    const float* emb = (const float*)d_in[0];
    const int*   ids = (const int*)d_in[1];
    float*       out = (float*)d_out;

    const int smem_bytes = (BM * AS_STRIDE + BN * BS_STRIDE + 2 * BM) * 4 + 2 * BM * 4;
    cudaFuncSetAttribute(loss_kernel, cudaFuncAttributeMaxDynamicSharedMemorySize, smem_bytes);

    init_accum_kernel<<<1, 1>>>();
    normalize_kernel<<<B_SZ / 8, 256>>>(emb);
    loss_kernel<<<B_SZ / BM, NTHREADS, smem_bytes>>>(ids);
    finalize_kernel<<<1, 1>>>(out);
}

// round 3
// speedup vs baseline: 11.5840x; 11.5840x over previous
#include <cuda_runtime.h>
#include <math.h>
#include <stdint.h>

#define B_SZ 8192
#define D_SZ 256
#define TILE_M 128
#define TILE_N 128
#define KCHUNK 64
#define COLGROUPS 2
#define TILES_PER_CG (B_SZ / TILE_N / COLGROUPS)   // 32
#define NCHUNKS (TILES_PER_CG * 4)                 // 128
#define NTHR 256
#define INV_T (1.0f / 0.07f)

#define AS_STRIDE 260                 // 256 + 4 pad -> banks (4*row + k) % 32
#define BS_STRIDE 68                  // 64 + 4 pad  -> banks (4*n + k) % 32
#define A_ELEMS (TILE_M * AS_STRIDE)  // 33280 floats
#define B_ELEMS (TILE_N * BS_STRIDE)  // 8704 floats
// smem: A (133120 B) + 2*B (69632 B) + ids 2*128 int (1024 B) = 203776 B
#define SMEM_TOTAL ((A_ELEMS + 2 * B_ELEMS) * 4 + 2 * TILE_N * 4)

static __device__ float g_norm[B_SZ * D_SZ];
static __device__ float g_rowAll[B_SZ];
static __device__ float g_rowPos[B_SZ];
static __device__ float g_loss;
static __device__ float g_count;

// ---------- PTX helpers (baseline compute_103 features only) ----------
__device__ __forceinline__ uint32_t smem_u32(const void* p) {
    uint32_t a;
    asm("{ .reg .u64 t; cvta.to.shared.u64 t, %1; cvt.u32.u64 %0, t; }" : "=r"(a) : "l"(p));
    return a;
}
#define CP_ASYNC16(dst, src) \
    asm volatile("cp.async.cg.shared.global [%0], [%1], 16;" :: "r"(dst), "l"(src))
#define CP_COMMIT() asm volatile("cp.async.commit_group;" ::: "memory")
#define CP_WAIT0()  asm volatile("cp.async.wait_group 0;" ::: "memory")

__device__ __forceinline__ void mma8(float* c, const uint32_t* a, const uint32_t* b) {
    asm volatile(
        "mma.sync.aligned.m16n8k8.row.col.f32.tf32.tf32.f32 "
        "{%0,%1,%2,%3}, {%4,%5,%6,%7}, {%8,%9}, {%0,%1,%2,%3};"
        : "+f"(c[0]), "+f"(c[1]), "+f"(c[2]), "+f"(c[3])
        : "r"(a[0]), "r"(a[1]), "r"(a[2]), "r"(a[3]), "r"(b[0]), "r"(b[1]));
}

// ---------- kernels ----------
__global__ void init_kernel() {
    int i = blockIdx.x * blockDim.x + threadIdx.x;
    if (i < B_SZ) { g_rowAll[i] = 0.0f; g_rowPos[i] = 0.0f; }
    if (i == 0) { g_loss = 0.0f; g_count = 0.0f; }
}

__global__ __launch_bounds__(256) void normalize_kernel(const float* __restrict__ emb) {
    int row = blockIdx.x * 8 + (threadIdx.x >> 5);
    int lane = threadIdx.x & 31;
    const float4* src = reinterpret_cast<const float4*>(emb) + (size_t)row * (D_SZ / 4);
    float4 v0 = src[lane], v1 = src[lane + 32];
    float s = v0.x*v0.x + v0.y*v0.y + v0.z*v0.z + v0.w*v0.w
            + v1.x*v1.x + v1.y*v1.y + v1.z*v1.z + v1.w*v1.w;
#pragma unroll
    for (int o = 16; o > 0; o >>= 1) s += __shfl_xor_sync(0xffffffffu, s, o);
    float sc = 1.0f / fmaxf(sqrtf(s), 1e-12f);
    float r[8] = {v0.x*sc, v0.y*sc, v0.z*sc, v0.w*sc, v1.x*sc, v1.y*sc, v1.z*sc, v1.w*sc};
#pragma unroll
    for (int i = 0; i < 8; i++)  // pre-round to tf32 (rna) so HMMA truncation is exact
        asm("cvt.rna.tf32.f32 %0, %1;" : "=f"(r[i]) : "f"(r[i]));
    float4* dst = reinterpret_cast<float4*>(g_norm) + (size_t)row * (D_SZ / 4);
    dst[lane]      = make_float4(r[0], r[1], r[2], r[3]);
    dst[lane + 32] = make_float4(r[4], r[5], r[6], r[7]);
}

__global__ __launch_bounds__(NTHR, 1) void loss_kernel(const int* __restrict__ ids) {
    extern __shared__ float smf[];
    float* As = smf;
    float* Bs = smf + A_ELEMS;
    int*  ids2 = reinterpret_cast<int*>(smf + A_ELEMS + 2 * B_ELEMS);
    const uint32_t sb = smem_u32(smf);
    const uint32_t bs_base_u32 = sb + A_ELEMS * 4;

    const int tid = threadIdx.x;
    const int lane = tid & 31, wid = tid >> 5;
    const int gid = lane >> 2, tig = lane & 3;
    const int wm = wid & 3, wn = wid >> 2;        // 4 (M) x 2 (N) warps
    const int stripe = blockIdx.x >> 1;
    const int cg = blockIdx.x & 1;
    const int r0 = stripe * TILE_M;
    const int cgbase = cg * (TILES_PER_CG * TILE_N);

    // this thread's cp.async slots: idx -> (n, k4)
    const int pf_n  = tid >> 4;
    const int pf_k4 = (tid & 15) << 2;

    // ---- resident A stripe (128 x 256) ----
#pragma unroll
    for (int i = 0; i < 32; i++) {
        int idx = tid + i * NTHR;
        int r = idx >> 6, c4 = (idx & 63) << 2;
        float4 v = *reinterpret_cast<const float4*>(g_norm + (size_t)(r0 + r) * D_SZ + c4);
        *reinterpret_cast<float4*>(As + r * AS_STRIDE + c4) = v;
    }
    // ---- chunk 0 via cp.async + ids tile 0 ----
    {
        const float* src = g_norm + (size_t)cgbase * D_SZ;
#pragma unroll
        for (int i = 0; i < 8; i++) {
            int n = pf_n + i * 16;
            uint32_t dst = bs_base_u32 + (uint32_t)(n * BS_STRIDE + pf_k4) * 4;
            CP_ASYNC16(dst, src + (size_t)n * D_SZ + pf_k4);
        }
        CP_COMMIT();
        if (tid < TILE_N) ids2[tid] = ids[cgbase + tid];
    }
    CP_WAIT0();
    __syncthreads();

    // per-thread rows (4): wm*32 + mf*16 + h*8 + gid
    int myRow[4], myId[4];
#pragma unroll
    for (int mf = 0; mf < 2; mf++)
#pragma unroll
        for (int h = 0; h < 2; h++) {
            int rr = wm * 32 + mf * 16 + h * 8 + gid;
            myRow[mf * 2 + h] = r0 + rr;
            myId[mf * 2 + h]  = ids[r0 + rr];
        }

    float acc[2][8][4];
#pragma unroll
    for (int mf = 0; mf < 2; mf++)
#pragma unroll
        for (int nf = 0; nf < 8; nf++)
#pragma unroll
            for (int q = 0; q < 4; q++) acc[mf][nf][q] = 0.0f;
    float allA[4] = {0.f, 0.f, 0.f, 0.f}, posA[4] = {0.f, 0.f, 0.f, 0.f};

    for (int t = 0; t < TILES_PER_CG; t++) {
        const int c0 = cgbase + t * TILE_N;
#pragma unroll 1
        for (int kc = 0; kc < 4; kc++) {
            const int ci = t * 4 + kc;
            const float* Bsc = Bs + (ci & 1) * B_ELEMS;

            // issue next chunk's cp.async into the other buffer
            if (ci + 1 < NCHUNKS) {
                const int nt = (ci + 1) >> 2, nkc = (ci + 1) & 3;
                const float* src = g_norm + (size_t)(cgbase + nt * TILE_N) * D_SZ + nkc * KCHUNK;
                uint32_t dstb = bs_base_u32 + (uint32_t)(((ci + 1) & 1) * B_ELEMS) * 4;
#pragma unroll
                for (int i = 0; i < 8; i++) {
                    int n = pf_n + i * 16;
                    uint32_t dst = dstb + (uint32_t)(n * BS_STRIDE + pf_k4) * 4;
                    CP_ASYNC16(dst, src + (size_t)n * D_SZ + pf_k4);
                }
                CP_COMMIT();
                if (kc == 0 && t + 1 < TILES_PER_CG && tid < TILE_N)
                    ids2[((t + 1) & 1) * TILE_N + tid] = ids[c0 + TILE_N + tid];
            }

            // compute: 8 k-steps of m16n8k8 over this chunk
            const float* Arow = As + (wm * 32 + gid) * AS_STRIDE + kc * KCHUNK + tig;
            const float* Brow = Bsc + (wn * 64 + gid) * BS_STRIDE + tig;
#pragma unroll
            for (int ks = 0; ks < 8; ks++) {
                uint32_t a[2][4], b[8][2];
#pragma unroll
                for (int mf = 0; mf < 2; mf++) {
                    const uint32_t* ap = reinterpret_cast<const uint32_t*>(
                        Arow + mf * 16 * AS_STRIDE + ks * 8);
                    a[mf][0] = ap[0];
                    a[mf][1] = ap[8 * AS_STRIDE];
                    a[mf][2] = ap[4];
                    a[mf][3] = ap[8 * AS_STRIDE + 4];
                }
#pragma unroll
                for (int nf = 0; nf < 8; nf++) {
                    const uint32_t* bp = reinterpret_cast<const uint32_t*>(
                        Brow + nf * 8 * BS_STRIDE + ks * 8);
                    b[nf][0] = bp[0];
                    b[nf][1] = bp[4];
                }
#pragma unroll
                for (int mf = 0; mf < 2; mf++)
#pragma unroll
                    for (int nf = 0; nf < 8; nf++)
                        mma8(acc[mf][nf], a[mf], b[nf]);
            }
            CP_WAIT0();
            __syncthreads();
        }

        // ---- epilogue tile t: exp, diag mask, pos/all accumulate ----
        const int* idsB = ids2 + (t & 1) * TILE_N;
#pragma unroll
        for (int mf = 0; mf < 2; mf++) {
#pragma unroll
            for (int nf = 0; nf < 8; nf++) {
                const int colb = wn * 64 + nf * 8 + 2 * tig;
                const int gj0 = c0 + colb, gj1 = gj0 + 1;
                const int idb0 = idsB[colb], idb1 = idsB[colb + 1];
                float e00 = __expf(acc[mf][nf][0] * INV_T);
                float e01 = __expf(acc[mf][nf][1] * INV_T);
                float e10 = __expf(acc[mf][nf][2] * INV_T);
                float e11 = __expf(acc[mf][nf][3] * INV_T);
                if (myRow[mf * 2 + 0] == gj0) e00 = 0.0f;
                if (myRow[mf * 2 + 0] == gj1) e01 = 0.0f;
                if (myRow[mf * 2 + 1] == gj0) e10 = 0.0f;
                if (myRow[mf * 2 + 1] == gj1) e11 = 0.0f;
                allA[mf * 2 + 0] += e00 + e01;
                allA[mf * 2 + 1] += e10 + e11;
                posA[mf * 2 + 0] += (myId[mf * 2 + 0] == idb0 ? e00 : 0.0f)
                                  + (myId[mf * 2 + 0] == idb1 ? e01 : 0.0f);
                posA[mf * 2 + 1] += (myId[mf * 2 + 1] == idb0 ? e10 : 0.0f)
                                  + (myId[mf * 2 + 1] == idb1 ? e11 : 0.0f);
#pragma unroll
                for (int q = 0; q < 4; q++) acc[mf][nf][q] = 0.0f;
            }
        }
    }

    // fold across the quad (threads sharing rows differ only in tig = lane&3)
#pragma unroll
    for (int q = 0; q < 4; q++) {
        float va = allA[q], vp = posA[q];
        va += __shfl_xor_sync(0xffffffffu, va, 1);
        va += __shfl_xor_sync(0xffffffffu, va, 2);
        vp += __shfl_xor_sync(0xffffffffu, vp, 1);
        vp += __shfl_xor_sync(0xffffffffu, vp, 2);
        if (tig == 0) {
            atomicAdd(&g_rowAll[myRow[q]], va);
            atomicAdd(&g_rowPos[myRow[q]], vp);
        }
    }
}

__global__ __launch_bounds__(256) void reduce_kernel() {
    __shared__ float sL[8], sC[8];
    int i = blockIdx.x * 256 + threadIdx.x;
    float p = g_rowPos[i], a = g_rowAll[i];
    float pr = 0.0f, vd = 0.0f;
    if (p > 0.0f) { pr = -logf(p / a); vd = 1.0f; }
#pragma unroll
    for (int o = 16; o > 0; o >>= 1) {
        pr += __shfl_xor_sync(0xffffffffu, pr, o);
        vd += __shfl_xor_sync(0xffffffffu, vd, o);
    }
    int w = threadIdx.x >> 5;
    if ((threadIdx.x & 31) == 0) { sL[w] = pr; sC[w] = vd; }
    __syncthreads();
    if (threadIdx.x < 8) {
        pr = sL[threadIdx.x]; sC[threadIdx.x] = sC[threadIdx.x];
        float v2 = sC[threadIdx.x];
#pragma unroll
        for (int o = 4; o > 0; o >>= 1) {
            pr += __shfl_xor_sync(0xffu, pr, o);
            v2 += __shfl_xor_sync(0xffu, v2, o);
        }
        if (threadIdx.x == 0) { atomicAdd(&g_loss, pr); atomicAdd(&g_count, v2); }
    }
}

__global__ void finalize_kernel(float* __restrict__ out) {
    out[0] = g_loss / fmaxf(g_count, 1.0f);
}

extern "C" void kernel_launch(void* const* d_in, const int* in_sizes, int n_in,
                              void* d_out, int out_size) {
    const float* emb = (const float*)d_in[0];
    const int*   ids = (const int*)d_in[1];
    float*       out = (float*)d_out;

    cudaFuncSetAttribute(loss_kernel, cudaFuncAttributeMaxDynamicSharedMemorySize, SMEM_TOTAL);

    init_kernel<<<(B_SZ + 255) / 256, 256>>>();
    normalize_kernel<<<B_SZ / 8, 256>>>(emb);
    loss_kernel<<<64 * COLGROUPS, NTHR, SMEM_TOTAL>>>(ids);
    reduce_kernel<<<B_SZ / 256, 256>>>();
    finalize_kernel<<<1, 1>>>(out);
}

// round 4
// speedup vs baseline: 22.2959x; 1.9247x over previous
#include <cuda_runtime.h>
#include <cuda_fp16.h>
#include <math.h>
#include <stdint.h>

#define B_SZ 8192
#define D_SZ 256
#define TILE_M 128
#define TILE_N 128
#define COLGROUPS 2
#define TILES_PER_CG (B_SZ / TILE_N / COLGROUPS)   // 32
#define NTHR 256
#define INV_T (1.0f / 0.07f)

#define S_STRIDE 264                    // 256 + 8 halves pad: 528 B/row -> ldmatrix conflict-free
#define TILE_ELEMS (TILE_M * S_STRIDE)  // 33792 halves = 67584 B
// smem: A tile + 2 B tiles + 2x128 ids
#define SMEM_TOTAL (3 * TILE_ELEMS * 2 + 2 * TILE_N * 4)

static __device__ __half g_h[B_SZ * D_SZ];     // normalized fp16 embeddings (4 MB)
static __device__ float g_rowAll[B_SZ];
static __device__ float g_rowPos[B_SZ];
static __device__ float g_loss;
static __device__ float g_count;

// ---------- PTX helpers (baseline compute_103 features only) ----------
__device__ __forceinline__ uint32_t smem_u32(const void* p) {
    uint32_t a;
    asm("{ .reg .u64 t; cvta.to.shared.u64 t, %1; cvt.u32.u64 %0, t; }" : "=r"(a) : "l"(p));
    return a;
}
#define CP_ASYNC16(dst, src) \
    asm volatile("cp.async.cg.shared.global [%0], [%1], 16;" :: "r"(dst), "l"(src))
#define CP_COMMIT() asm volatile("cp.async.commit_group;" ::: "memory")
#define CP_WAIT0()  asm volatile("cp.async.wait_group 0;" ::: "memory")

#define LDSM_X4(r0, r1, r2, r3, a) \
    asm volatile("ldmatrix.sync.aligned.m8n8.x4.shared.b16 {%0,%1,%2,%3}, [%4];" \
                 : "=r"(r0), "=r"(r1), "=r"(r2), "=r"(r3) : "r"(a))

__device__ __forceinline__ void mma16(float* c, const uint32_t* a, const uint32_t* b) {
    asm volatile(
        "mma.sync.aligned.m16n8k16.row.col.f32.f16.f16.f32 "
        "{%0,%1,%2,%3}, {%4,%5,%6,%7}, {%8,%9}, {%0,%1,%2,%3};"
        : "+f"(c[0]), "+f"(c[1]), "+f"(c[2]), "+f"(c[3])
        : "r"(a[0]), "r"(a[1]), "r"(a[2]), "r"(a[3]), "r"(b[0]), "r"(b[1]));
}

// async-copy one 128x256 fp16 tile (rows contiguous in gmem) into padded smem
__device__ __forceinline__ void load_tile(uint32_t dst, const __half* src, int tid) {
#pragma unroll
    for (int p = 0; p < 16; p++) {
        int idx = tid + p * NTHR;
        int row = idx >> 5, ch = idx & 31;          // 32 x 16B chunks per row
        CP_ASYNC16(dst + (uint32_t)(row * S_STRIDE + ch * 8) * 2,
                   src + (size_t)row * D_SZ + ch * 8);
    }
}

// ---------- kernels ----------
__global__ void init_kernel() {
    int i = blockIdx.x * blockDim.x + threadIdx.x;
    if (i < B_SZ) { g_rowAll[i] = 0.0f; g_rowPos[i] = 0.0f; }
    if (i == 0) { g_loss = 0.0f; g_count = 0.0f; }
}

// one warp per row: fp32 L2-normalize, store fp16
__global__ __launch_bounds__(256) void normalize_kernel(const float* __restrict__ emb) {
    int row = blockIdx.x * 8 + (threadIdx.x >> 5);
    int lane = threadIdx.x & 31;
    const float4* src = reinterpret_cast<const float4*>(emb) + (size_t)row * (D_SZ / 4);
    float4 v0 = src[lane * 2], v1 = src[lane * 2 + 1];   // elements lane*8 .. lane*8+7
    float s = v0.x*v0.x + v0.y*v0.y + v0.z*v0.z + v0.w*v0.w
            + v1.x*v1.x + v1.y*v1.y + v1.z*v1.z + v1.w*v1.w;
#pragma unroll
    for (int o = 16; o > 0; o >>= 1) s += __shfl_xor_sync(0xffffffffu, s, o);
    float sc = 1.0f / fmaxf(sqrtf(s), 1e-12f);
    __half2 h[4];
    h[0] = __floats2half2_rn(v0.x * sc, v0.y * sc);
    h[1] = __floats2half2_rn(v0.z * sc, v0.w * sc);
    h[2] = __floats2half2_rn(v1.x * sc, v1.y * sc);
    h[3] = __floats2half2_rn(v1.z * sc, v1.w * sc);
    *reinterpret_cast<uint4*>(g_h + (size_t)row * D_SZ + lane * 8) =
        *reinterpret_cast<uint4*>(h);
}

__global__ __launch_bounds__(NTHR, 1) void loss_kernel(const int* __restrict__ ids) {
    extern __shared__ __half smh[];
    const uint32_t sb = smem_u32(smh);
    const uint32_t sbA = sb;
    const uint32_t sbB0 = sb + TILE_ELEMS * 2;
    int* ids2 = reinterpret_cast<int*>(smh + 3 * TILE_ELEMS);

    const int tid = threadIdx.x;
    const int lane = tid & 31, wid = tid >> 5;
    const int gid = lane >> 2, tig = lane & 3;
    const int wm = wid & 3, wn = wid >> 2;           // 4 (M) x 2 (N) warps
    const int stripe = blockIdx.x >> 1;
    const int cg = blockIdx.x & 1;
    const int r0 = stripe * TILE_M;
    const int cgbase = cg * (TILES_PER_CG * TILE_N);

    // ldmatrix per-lane source offsets (half units)
    // A (x4): q = lane>>3: rowoff = ((lane>>3)&1)*8 + (lane&7); koff = (lane>>4)*8
    const int a_rowoff = (((lane >> 3) & 1) << 3) + (lane & 7);
    const int a_koff   = (lane >> 4) << 3;
    const uint32_t a_base = sbA + (uint32_t)((wm * 32 + a_rowoff) * S_STRIDE + a_koff) * 2;
    // B (x4, two n-blocks): noff = (lane>>4)*8 + (lane&7); koff = ((lane>>3)&1)*8
    const int b_noff = ((lane >> 4) << 3) + (lane & 7);
    const int b_koff = ((lane >> 3) & 1) << 3;
    const uint32_t b_lane_off = (uint32_t)((wn * 64 + b_noff) * S_STRIDE + b_koff) * 2;

    // prologue: A stripe + B tile 0 + ids tile 0
    load_tile(sbA, g_h + (size_t)r0 * D_SZ, tid);
    load_tile(sbB0, g_h + (size_t)cgbase * D_SZ, tid);
    CP_COMMIT();
    if (tid < TILE_N) ids2[tid] = ids[cgbase + tid];

    int myRow[4], myId[4];
#pragma unroll
    for (int mf = 0; mf < 2; mf++)
#pragma unroll
        for (int h = 0; h < 2; h++) {
            int rr = wm * 32 + mf * 16 + h * 8 + gid;
            myRow[mf * 2 + h] = r0 + rr;
            myId[mf * 2 + h]  = ids[r0 + rr];
        }

    float acc[2][8][4];
#pragma unroll
    for (int mf = 0; mf < 2; mf++)
#pragma unroll
        for (int nf = 0; nf < 8; nf++)
#pragma unroll
            for (int q = 0; q < 4; q++) acc[mf][nf][q] = 0.0f;
    float allA[4] = {0.f, 0.f, 0.f, 0.f}, posA[4] = {0.f, 0.f, 0.f, 0.f};

    CP_WAIT0();
    __syncthreads();

#pragma unroll 1
    for (int t = 0; t < TILES_PER_CG; t++) {
        const int c0 = cgbase + t * TILE_N;
        const uint32_t bufB = sbB0 + (uint32_t)(t & 1) * (TILE_ELEMS * 2);

        // issue next tile into the other buffer (overlaps with compute+epilogue)
        if (t + 1 < TILES_PER_CG) {
            load_tile(sbB0 + (uint32_t)((t + 1) & 1) * (TILE_ELEMS * 2),
                      g_h + (size_t)(c0 + TILE_N) * D_SZ, tid);
            CP_COMMIT();
            if (tid < TILE_N) ids2[((t + 1) & 1) * TILE_N + tid] = ids[c0 + TILE_N + tid];
        }

        // compute: 16 k-steps of m16n8k16
#pragma unroll
        for (int ks = 0; ks < 16; ks++) {
            uint32_t a[2][4], b[8][2];
#pragma unroll
            for (int mf = 0; mf < 2; mf++) {
                uint32_t addr = a_base + (uint32_t)(mf * 16 * S_STRIDE + ks * 16) * 2;
                LDSM_X4(a[mf][0], a[mf][1], a[mf][2], a[mf][3], addr);
            }
#pragma unroll
            for (int np = 0; np < 4; np++) {
                uint32_t addr = bufB + b_lane_off + (uint32_t)(np * 16 * S_STRIDE + ks * 16) * 2;
                LDSM_X4(b[2*np][0], b[2*np][1], b[2*np+1][0], b[2*np+1][1], addr);
            }
#pragma unroll
            for (int mf = 0; mf < 2; mf++)
#pragma unroll
                for (int nf = 0; nf < 8; nf++)
                    mma16(acc[mf][nf], a[mf], b[nf]);
        }

        // epilogue: exp, diag mask, pos/all accumulate (registers only + ids smem)
        const int* idsB = ids2 + (t & 1) * TILE_N;
#pragma unroll
        for (int mf = 0; mf < 2; mf++) {
#pragma unroll
            for (int nf = 0; nf < 8; nf++) {
                const int colb = wn * 64 + nf * 8 + 2 * tig;
                const int gj0 = c0 + colb, gj1 = gj0 + 1;
                const int idb0 = idsB[colb], idb1 = idsB[colb + 1];
                float e00 = __expf(acc[mf][nf][0] * INV_T);
                float e01 = __expf(acc[mf][nf][1] * INV_T);
                float e10 = __expf(acc[mf][nf][2] * INV_T);
                float e11 = __expf(acc[mf][nf][3] * INV_T);
                if (myRow[mf * 2 + 0] == gj0) e00 = 0.0f;
                if (myRow[mf * 2 + 0] == gj1) e01 = 0.0f;
                if (myRow[mf * 2 + 1] == gj0) e10 = 0.0f;
                if (myRow[mf * 2 + 1] == gj1) e11 = 0.0f;
                allA[mf * 2 + 0] += e00 + e01;
                allA[mf * 2 + 1] += e10 + e11;
                posA[mf * 2 + 0] += (myId[mf * 2 + 0] == idb0 ? e00 : 0.0f)
                                  + (myId[mf * 2 + 0] == idb1 ? e01 : 0.0f);
                posA[mf * 2 + 1] += (myId[mf * 2 + 1] == idb0 ? e10 : 0.0f)
                                  + (myId[mf * 2 + 1] == idb1 ? e11 : 0.0f);
#pragma unroll
                for (int q = 0; q < 4; q++) acc[mf][nf][q] = 0.0f;
            }
        }

        CP_WAIT0();
        __syncthreads();
    }

    // fold across the quad (threads sharing rows differ only in tig)
#pragma unroll
    for (int q = 0; q < 4; q++) {
        float va = allA[q], vp = posA[q];
        va += __shfl_xor_sync(0xffffffffu, va, 1);
        va += __shfl_xor_sync(0xffffffffu, va, 2);
        vp += __shfl_xor_sync(0xffffffffu, vp, 1);
        vp += __shfl_xor_sync(0xffffffffu, vp, 2);
        if (tig == 0) {
            atomicAdd(&g_rowAll[myRow[q]], va);
            atomicAdd(&g_rowPos[myRow[q]], vp);
        }
    }
}

__global__ __launch_bounds__(256) void reduce_kernel() {
    __shared__ float sL[8], sC[8];
    int i = blockIdx.x * 256 + threadIdx.x;
    float p = g_rowPos[i], a = g_rowAll[i];
    float pr = 0.0f, vd = 0.0f;
    if (p > 0.0f) { pr = -logf(p / a); vd = 1.0f; }
#pragma unroll
    for (int o = 16; o > 0; o >>= 1) {
        pr += __shfl_xor_sync(0xffffffffu, pr, o);
        vd += __shfl_xor_sync(0xffffffffu, vd, o);
    }
    int w = threadIdx.x >> 5;
    if ((threadIdx.x & 31) == 0) { sL[w] = pr; sC[w] = vd; }
    __syncthreads();
    if (threadIdx.x < 8) {
        pr = sL[threadIdx.x];
        float v2 = sC[threadIdx.x];
#pragma unroll
        for (int o = 4; o > 0; o >>= 1) {
            pr += __shfl_xor_sync(0xffu, pr, o);
            v2 += __shfl_xor_sync(0xffu, v2, o);
        }
        if (threadIdx.x == 0) { atomicAdd(&g_loss, pr); atomicAdd(&g_count, v2); }
    }
}

__global__ void finalize_kernel(float* __restrict__ out) {
    out[0] = g_loss / fmaxf(g_count, 1.0f);
}

extern "C" void kernel_launch(void* const* d_in, const int* in_sizes, int n_in,
                              void* d_out, int out_size) {
    const float* emb = (const float*)d_in[0];
    const int*   ids = (const int*)d_in[1];
    float*       out = (float*)d_out;

    cudaFuncSetAttribute(loss_kernel, cudaFuncAttributeMaxDynamicSharedMemorySize, SMEM_TOTAL);

    init_kernel<<<(B_SZ + 255) / 256, 256>>>();
    normalize_kernel<<<B_SZ / 8, 256>>>(emb);
    loss_kernel<<<64 * COLGROUPS, NTHR, SMEM_TOTAL>>>(ids);
    reduce_kernel<<<B_SZ / 256, 256>>>();
    finalize_kernel<<<1, 1>>>(out);
}

// round 5
// speedup vs baseline: 25.9017x; 1.1617x over previous
#include <cuda_runtime.h>
#include <cuda_fp16.h>
#include <math.h>
#include <stdint.h>

#define B_SZ 8192
#define D_SZ 256
#define TILE 128
#define NSTRIPES (B_SZ / TILE)                     // 64
#define NJOBS (NSTRIPES * (NSTRIPES + 1) / 2)      // 2080
#define GRID 296
#define NTHR 256
#define INV_T (1.0f / 0.07f)

#define S_STRIDE 264                               // 256 + 8 halves pad (ldmatrix conflict-free)
#define SLOT_HALVES (TILE * S_STRIDE)              // 33792
#define SLOT_BYTES (SLOT_HALVES * 2)               // 67584
#define IDS_BYTE_OFF (3 * SLOT_BYTES)              // 202752
#define SMEM_TOTAL (3 * SLOT_BYTES + 3 * TILE * 4) // 204288

static __device__ __half g_h[B_SZ * D_SZ];         // normalized fp16 embeddings (4 MB)
static __device__ float g_rowAll[B_SZ];
static __device__ float g_rowPos[B_SZ];

// ---------- PTX helpers (baseline compute_103 features only) ----------
__device__ __forceinline__ uint32_t smem_u32(const void* p) {
    uint32_t a;
    asm("{ .reg .u64 t; cvta.to.shared.u64 t, %1; cvt.u32.u64 %0, t; }" : "=r"(a) : "l"(p));
    return a;
}
#define CP_ASYNC16(dst, src) \
    asm volatile("cp.async.cg.shared.global [%0], [%1], 16;" :: "r"(dst), "l"(src))
#define CP_COMMIT() asm volatile("cp.async.commit_group;" ::: "memory")
#define CP_WAIT0()  asm volatile("cp.async.wait_group 0;" ::: "memory")

#define LDSM_X4(r0, r1, r2, r3, a) \
    asm volatile("ldmatrix.sync.aligned.m8n8.x4.shared.b16 {%0,%1,%2,%3}, [%4];" \
                 : "=r"(r0), "=r"(r1), "=r"(r2), "=r"(r3) : "r"(a))

__device__ __forceinline__ void mma16(float* c, const uint32_t* a, const uint32_t* b) {
    asm volatile(
        "mma.sync.aligned.m16n8k16.row.col.f32.f16.f16.f32 "
        "{%0,%1,%2,%3}, {%4,%5,%6,%7}, {%8,%9}, {%0,%1,%2,%3};"
        : "+f"(c[0]), "+f"(c[1]), "+f"(c[2]), "+f"(c[3])
        : "r"(a[0]), "r"(a[1]), "r"(a[2]), "r"(a[3]), "r"(b[0]), "r"(b[1]));
}

// async-copy one 128x256 fp16 stripe + its 128 ids into a smem slot
__device__ __forceinline__ void load_stripe(uint32_t slot_base, uint32_t ids_base,
                                            int stripe, const int* ids, int tid) {
    const __half* src = g_h + (size_t)stripe * TILE * D_SZ;
#pragma unroll
    for (int p = 0; p < 16; p++) {
        int idx = tid + p * NTHR;
        int row = idx >> 5, ch = idx & 31;          // 32 x 16B chunks per row
        CP_ASYNC16(slot_base + (uint32_t)(row * S_STRIDE + ch * 8) * 2,
                   src + (size_t)row * D_SZ + ch * 8);
    }
    if (tid < 32)   // 128 ints = 512 B
        CP_ASYNC16(ids_base + tid * 16, ids + stripe * TILE + tid * 4);
}

__device__ __forceinline__ void job_ij(int q, int& i, int& j) {
    int ii = 0, base = 0;
    while (base + (NSTRIPES - ii) <= q) { base += NSTRIPES - ii; ii++; }
    i = ii; j = ii + (q - base);
}

// ---------- kernels ----------
// fp32 L2-normalize -> fp16; also zeroes the per-row accumulators
__global__ __launch_bounds__(256) void normalize_kernel(const float* __restrict__ emb) {
    int row = blockIdx.x * 8 + (threadIdx.x >> 5);
    int lane = threadIdx.x & 31;
    const float4* src = reinterpret_cast<const float4*>(emb) + (size_t)row * (D_SZ / 4);
    float4 v0 = src[lane * 2], v1 = src[lane * 2 + 1];
    float s = v0.x*v0.x + v0.y*v0.y + v0.z*v0.z + v0.w*v0.w
            + v1.x*v1.x + v1.y*v1.y + v1.z*v1.z + v1.w*v1.w;
#pragma unroll
    for (int o = 16; o > 0; o >>= 1) s += __shfl_xor_sync(0xffffffffu, s, o);
    float sc = 1.0f / fmaxf(sqrtf(s), 1e-12f);
    __half2 h[4];
    h[0] = __floats2half2_rn(v0.x * sc, v0.y * sc);
    h[1] = __floats2half2_rn(v0.z * sc, v0.w * sc);
    h[2] = __floats2half2_rn(v1.x * sc, v1.y * sc);
    h[3] = __floats2half2_rn(v1.z * sc, v1.w * sc);
    *reinterpret_cast<uint4*>(g_h + (size_t)row * D_SZ + lane * 8) =
        *reinterpret_cast<uint4*>(h);
    if (lane == 0) { g_rowAll[row] = 0.0f; g_rowPos[row] = 0.0f; }
}

__global__ __launch_bounds__(NTHR, 1) void loss_kernel(const int* __restrict__ ids) {
    extern __shared__ __half smh[];
    const uint32_t sb = smem_u32(smh);
    const uint32_t ids_sb = sb + IDS_BYTE_OFF;
    int* ids_s = reinterpret_cast<int*>(reinterpret_cast<char*>(smh) + IDS_BYTE_OFF);

    const int tid = threadIdx.x;
    const int lane = tid & 31, wid = tid >> 5;
    const int gid = lane >> 2, tig = lane & 3;
    const int wm = wid & 3, wn = wid >> 2;           // 4 (M) x 2 (N) warps

    // ldmatrix per-lane offsets (half units)
    const int a_rowoff = (((lane >> 3) & 1) << 3) + (lane & 7);
    const int a_koff   = (lane >> 4) << 3;
    const uint32_t a_lane = (uint32_t)((wm * 32 + a_rowoff) * S_STRIDE + a_koff) * 2;
    const int b_noff = ((lane >> 4) << 3) + (lane & 7);
    const int b_koff = ((lane >> 3) & 1) << 3;
    const uint32_t b_lane = (uint32_t)((wn * 64 + b_noff) * S_STRIDE + b_koff) * 2;

    const int qs = (int)(((long long)blockIdx.x * NJOBS) / GRID);
    const int qe = (int)(((long long)(blockIdx.x + 1) * NJOBS) / GRID);

    int slot_stripe[3] = {-1, -1, -1};

    // prologue: load first job's stripes
    int i, j;
    job_ij(qs, i, j);
    load_stripe(sb, ids_sb, i, ids, tid);
    slot_stripe[0] = i;
    if (j != i) {
        load_stripe(sb + SLOT_BYTES, ids_sb + TILE * 4, j, ids, tid);
        slot_stripe[1] = j;
    }
    CP_COMMIT();
    CP_WAIT0();
    __syncthreads();

    float acc[2][8][4];
#pragma unroll
    for (int mf = 0; mf < 2; mf++)
#pragma unroll
        for (int nf = 0; nf < 8; nf++)
#pragma unroll
            for (int q = 0; q < 4; q++) acc[mf][nf][q] = 0.0f;

#pragma unroll 1
    for (int q = qs; q < qe; q++) {
        job_ij(q, i, j);
        int slotA = 0, slotB = 0;
#pragma unroll
        for (int k = 0; k < 3; k++) {
            if (slot_stripe[k] == i) slotA = k;
            if (slot_stripe[k] == j) slotB = k;
        }

        // prefetch next job's (single) new stripe into a free slot
        if (q + 1 < qe) {
            int i2, j2;
            job_ij(q + 1, i2, j2);
            int ns = (i2 != i && i2 != j) ? i2 : ((j2 != i && j2 != j) ? j2 : -1);
            if (ns >= 0) {
                bool have = (slot_stripe[0] == ns) | (slot_stripe[1] == ns) | (slot_stripe[2] == ns);
                if (!have) {
                    int fs = 0;
#pragma unroll
                    for (int k = 2; k >= 0; k--)
                        if (k != slotA && k != slotB) fs = k;
                    load_stripe(sb + (uint32_t)fs * SLOT_BYTES, ids_sb + (uint32_t)fs * TILE * 4,
                                ns, ids, tid);
                    slot_stripe[fs] = ns;
                }
            }
            CP_COMMIT();
        }

        // ---- MMA: 128x128x256 from slots ----
        const uint32_t a_base = sb + (uint32_t)slotA * SLOT_BYTES + a_lane;
        const uint32_t b_base = sb + (uint32_t)slotB * SLOT_BYTES + b_lane;
#pragma unroll
        for (int ks = 0; ks < 16; ks++) {
            uint32_t a[2][4], b[8][2];
#pragma unroll
            for (int mf = 0; mf < 2; mf++) {
                uint32_t addr = a_base + (uint32_t)(mf * 16 * S_STRIDE + ks * 16) * 2;
                LDSM_X4(a[mf][0], a[mf][1], a[mf][2], a[mf][3], addr);
            }
#pragma unroll
            for (int np = 0; np < 4; np++) {
                uint32_t addr = b_base + (uint32_t)(np * 16 * S_STRIDE + ks * 16) * 2;
                LDSM_X4(b[2*np][0], b[2*np][1], b[2*np+1][0], b[2*np+1][1], addr);
            }
#pragma unroll
            for (int mf = 0; mf < 2; mf++)
#pragma unroll
                for (int nf = 0; nf < 8; nf++)
                    mma16(acc[mf][nf], a[mf], b[nf]);
        }

        // ---- epilogue: exp once, feed row sums (stripe i) and col sums (stripe j) ----
        const int* idA = ids_s + slotA * TILE;
        const int* idB = ids_s + slotB * TILE;
        const bool diag = (i == j);

        int myId[4];
        float rA[4] = {0.f, 0.f, 0.f, 0.f}, rP[4] = {0.f, 0.f, 0.f, 0.f};
        float cA[16], cP[16];
#pragma unroll
        for (int c = 0; c < 16; c++) { cA[c] = 0.0f; cP[c] = 0.0f; }
#pragma unroll
        for (int mf = 0; mf < 2; mf++)
#pragma unroll
            for (int h = 0; h < 2; h++)
                myId[mf * 2 + h] = idA[wm * 32 + mf * 16 + h * 8 + gid];

#pragma unroll
        for (int mf = 0; mf < 2; mf++) {
#pragma unroll
            for (int nf = 0; nf < 8; nf++) {
                const int colb = wn * 64 + nf * 8 + 2 * tig;
                const int idb0 = idB[colb], idb1 = idB[colb + 1];
#pragma unroll
                for (int h = 0; h < 2; h++) {
                    const int rowl = wm * 32 + mf * 16 + h * 8 + gid;
                    float e0 = __expf(acc[mf][nf][2*h + 0] * INV_T);
                    float e1 = __expf(acc[mf][nf][2*h + 1] * INV_T);
                    if (diag && rowl == colb)     e0 = 0.0f;
                    if (diag && rowl == colb + 1) e1 = 0.0f;
                    const int r = mf * 2 + h;
                    rA[r] += e0 + e1;
                    float p0 = (myId[r] == idb0) ? e0 : 0.0f;
                    float p1 = (myId[r] == idb1) ? e1 : 0.0f;
                    rP[r] += p0 + p1;
                    cA[nf*2 + 0] += e0;  cA[nf*2 + 1] += e1;
                    cP[nf*2 + 0] += p0;  cP[nf*2 + 1] += p1;
                    acc[mf][nf][2*h + 0] = 0.0f;
                    acc[mf][nf][2*h + 1] = 0.0f;
                }
            }
        }

        // row side: fold across the quad (tig), atomics from tig==0 lanes
#pragma unroll
        for (int r = 0; r < 4; r++) {
            float va = rA[r], vp = rP[r];
            va += __shfl_xor_sync(0xffffffffu, va, 1);
            va += __shfl_xor_sync(0xffffffffu, va, 2);
            vp += __shfl_xor_sync(0xffffffffu, vp, 1);
            vp += __shfl_xor_sync(0xffffffffu, vp, 2);
            if (tig == 0) {
                int grow = i * TILE + wm * 32 + (r >> 1) * 16 + (r & 1) * 8 + gid;
                atomicAdd(&g_rowAll[grow], va);
                atomicAdd(&g_rowPos[grow], vp);
            }
        }
        // col side (transpose contribution): fold across gid, atomics from gid==0 lanes
        if (!diag) {
#pragma unroll
            for (int c = 0; c < 16; c++) {
                float va = cA[c], vp = cP[c];
                va += __shfl_xor_sync(0xffffffffu, va, 4);
                va += __shfl_xor_sync(0xffffffffu, va, 8);
                va += __shfl_xor_sync(0xffffffffu, va, 16);
                vp += __shfl_xor_sync(0xffffffffu, vp, 4);
                vp += __shfl_xor_sync(0xffffffffu, vp, 8);
                vp += __shfl_xor_sync(0xffffffffu, vp, 16);
                if (gid == 0) {
                    int grow = j * TILE + wn * 64 + (c >> 1) * 8 + 2 * tig + (c & 1);
                    atomicAdd(&g_rowAll[grow], va);
                    atomicAdd(&g_rowPos[grow], vp);
                }
            }
        }

        CP_WAIT0();
        __syncthreads();
    }
}

__global__ __launch_bounds__(1024) void final_reduce(float* __restrict__ out) {
    __shared__ float sL[32], sC[32];
    const int tid = threadIdx.x;
    float pr = 0.0f, vd = 0.0f;
#pragma unroll
    for (int it = 0; it < B_SZ / 1024; it++) {
        int r = tid + it * 1024;
        float p = g_rowPos[r], a = g_rowAll[r];
        if (p > 0.0f) { pr += -logf(p / a); vd += 1.0f; }
    }
#pragma unroll
    for (int o = 16; o > 0; o >>= 1) {
        pr += __shfl_xor_sync(0xffffffffu, pr, o);
        vd += __shfl_xor_sync(0xffffffffu, vd, o);
    }
    if ((tid & 31) == 0) { sL[tid >> 5] = pr; sC[tid >> 5] = vd; }
    __syncthreads();
    if (tid < 32) {
        pr = sL[tid]; vd = sC[tid];
#pragma unroll
        for (int o = 16; o > 0; o >>= 1) {
            pr += __shfl_xor_sync(0xffffffffu, pr, o);
            vd += __shfl_xor_sync(0xffffffffu, vd, o);
        }
        if (tid == 0) out[0] = pr / fmaxf(vd, 1.0f);
    }
}

extern "C" void kernel_launch(void* const* d_in, const int* in_sizes, int n_in,
                              void* d_out, int out_size) {
    const float* emb = (const float*)d_in[0];
    const int*   ids = (const int*)d_in[1];
    float*       out = (float*)d_out;

    cudaFuncSetAttribute(loss_kernel, cudaFuncAttributeMaxDynamicSharedMemorySize, SMEM_TOTAL);

    normalize_kernel<<<B_SZ / 8, 256>>>(emb);
    loss_kernel<<<GRID, NTHR, SMEM_TOTAL>>>(ids);
    final_reduce<<<1, 1024>>>(out);
}